// round 16
// baseline (speedup 1.0000x reference)
#include <cuda_runtime.h>
#include <cuda_bf16.h>
#include <cstdint>

// ---------------------------------------------------------------------------
// BiARMA (2-layer ARMA GCN), N=100000, E=1e6, 128 -> 64 -> 40.
//
// deg[c] = #edges into c;  dinv = rsqrt(deg) (0 if deg==0), on the fly.
// g1   = dinv * (x @ W1i)            S1[c] += g1[row]  (fp32 vector atomics)
// R1   = x @ W1r + b1        (side stream, forked AFTER gemm1i: overlaps the
//                             LTS-bound scatter1 with tensor/L1-bound work)
// out1 = relu(dinv*S1 + R1)  (not materialized: fused into layer-2 A-loads)
// g2   = dinv * (out1 @ W2i)         S2[c] += g2[row]
// R2   = out1 @ W2r + b2 -> d_out    (side stream, overlaps gemm2i+scatter2)
// out  = relu(dinv*S2 + R2)          (in place over d_out)
//
// GEMMs: mma.sync.m16n8k16 bf16, 2-term split (Ah*Bh + Ah*Bl + Al*Bh);
// A direct-from-global (optionally fused relu(dinv*S+R)), B in static smem.
// Scatter: red.global.add.v4.f32 — LTS-bandwidth bound (~512MB through L2),
// algorithmically minimal; we overlap it instead of shrinking it.
//
// Arena 83.6 MB, NO ALIASING between concurrently-live regions:
//   R1 [0,64N)   S1 [64N,128N)   g1 [128N,192N) (dead after scatter1)
//   g2 [128N,168N) (over dead g1)   S2 [168N,208N)   R2 -> d_out
// ---------------------------------------------------------------------------

static constexpr int MAXN = 100000;

__device__ float g_deg  [MAXN];
__device__ float g_arena[(size_t)MAXN * 208];

// ---------------------------------------------------------------------------
__global__ void deg_kernel(const int* __restrict__ col, float* __restrict__ deg, int E) {
    int i = blockIdx.x * blockDim.x + threadIdx.x;
    if (i < E) atomicAdd(&deg[col[i]], 1.0f);
}

// ---------------------------------------------------------------------------
#define MMA_BF16(c_, a_, b0_, b1_)                                          \
    asm volatile("mma.sync.aligned.m16n8k16.row.col.f32.bf16.bf16.f32 "     \
                 "{%0,%1,%2,%3}, {%4,%5,%6,%7}, {%8,%9}, {%0,%1,%2,%3};"    \
                 : "+f"((c_)[0]), "+f"((c_)[1]), "+f"((c_)[2]), "+f"((c_)[3]) \
                 : "r"((a_)[0]), "r"((a_)[1]), "r"((a_)[2]), "r"((a_)[3]),  \
                   "r"(b0_), "r"(b1_))

__device__ __forceinline__ void split_bf16(float v, __nv_bfloat16& h, __nv_bfloat16& l) {
    h = __float2bfloat16(v);
    l = __float2bfloat16(v - __bfloat162float(h));
}

// Split a float2 into packed bf16x2 hi + residual lo.
__device__ __forceinline__ void cvt_split(float2 v, uint32_t& hi, uint32_t& lo) {
    uint32_t h;
    asm("cvt.rn.bf16x2.f32 %0, %1, %2;" : "=r"(h) : "f"(v.y), "f"(v.x));
    float hx = __uint_as_float(h << 16);
    float hy = __uint_as_float(h & 0xFFFF0000u);
    float rx = v.x - hx;
    float ry = v.y - hy;
    uint32_t l;
    asm("cvt.rn.bf16x2.f32 %0, %1, %2;" : "=r"(l) : "f"(ry), "f"(rx));
    hi = h; lo = l;
}

__device__ __forceinline__ float dinv_of(const float* deg, int node, int N) {
    if (node >= N) return 0.0f;
    float d = deg[node];
    return (d > 0.0f) ? rsqrtf(d) : 0.0f;
}

// ---------------------------------------------------------------------------
// Tensor-core GEMM, A direct-from-global, B in static smem.
// FUSEA=false: A[n,k] = X[n,k]
// FUSEA=true : A[n,k] = relu(dinv[n]*SA[n,k] + RA[n,k])   (out1 on the fly)
// ROOT=false (INIT): O[n] = dinv[n]*(A@W)[n]  and  S[n] = 0
// ROOT=true        : O[n] = (A@W)[n] + bias
// Block: 256 threads (8 warps), tile = 128 rows; warp owns 16 rows x NC cols.
// ---------------------------------------------------------------------------
template <int K, int NC, bool ROOT, bool FUSEA>
__global__ void __launch_bounds__(256)
gemm_mma(const float* __restrict__ X,
         const float* __restrict__ SA, const float* __restrict__ RA,
         const float* __restrict__ W,  const float* __restrict__ Bias,
         const float* __restrict__ deg,
         float* __restrict__ S, float* __restrict__ O, int N)
{
    constexpr int SB = K + 8;
    constexpr int NT = NC / 8;

    __shared__ __nv_bfloat16 Bh[NC * SB];
    __shared__ __nv_bfloat16 Bl[NC * SB];

    const int tid  = threadIdx.x;
    const int base = blockIdx.x * 128;

    for (int i = tid; i < K * NC; i += 256) {
        int k = i / NC, n = i - k * NC;
        __nv_bfloat16 h, l;
        split_bf16(W[i], h, l);
        Bh[n * SB + k] = h;
        Bl[n * SB + k] = l;
    }
    __syncthreads();

    const int warp = tid >> 5, lane = tid & 31;
    const int g = lane >> 2, t = lane & 3;

    const int r0 = base + warp * 16 + g;
    const int r1 = r0 + 8;
    const bool ok0 = r0 < N, ok1 = r1 < N;

    const float dv0 = (FUSEA || !ROOT) ? dinv_of(deg, r0, N) : 0.0f;
    const float dv1 = (FUSEA || !ROOT) ? dinv_of(deg, r1, N) : 0.0f;

    const float* X0  = FUSEA ? nullptr : X + (size_t)r0 * K;
    const float* X1  = FUSEA ? nullptr : X + (size_t)r1 * K;
    const float* S0  = FUSEA ? SA + (size_t)r0 * K : nullptr;
    const float* S1p = FUSEA ? SA + (size_t)r1 * K : nullptr;
    const float* R0  = FUSEA ? RA + (size_t)r0 * K : nullptr;
    const float* R1p = FUSEA ? RA + (size_t)r1 * K : nullptr;

    float acc[NT][4];
#pragma unroll
    for (int nt = 0; nt < NT; nt++)
#pragma unroll
        for (int j = 0; j < 4; j++) acc[nt][j] = 0.0f;

#pragma unroll
    for (int ks = 0; ks < K; ks += 16) {
        const int k0 = ks + t * 2;

        float2 v0, v1, v2, v3;
        if (FUSEA) {
            float2 z = make_float2(0.f, 0.f);
            float2 s0 = ok0 ? __ldg(reinterpret_cast<const float2*>(S0 + k0))     : z;
            float2 s1 = ok1 ? __ldg(reinterpret_cast<const float2*>(S1p + k0))    : z;
            float2 s2 = ok0 ? __ldg(reinterpret_cast<const float2*>(S0 + k0 + 8)) : z;
            float2 s3 = ok1 ? __ldg(reinterpret_cast<const float2*>(S1p + k0 + 8)): z;
            float2 q0 = ok0 ? __ldg(reinterpret_cast<const float2*>(R0 + k0))     : z;
            float2 q1 = ok1 ? __ldg(reinterpret_cast<const float2*>(R1p + k0))    : z;
            float2 q2 = ok0 ? __ldg(reinterpret_cast<const float2*>(R0 + k0 + 8)) : z;
            float2 q3 = ok1 ? __ldg(reinterpret_cast<const float2*>(R1p + k0 + 8)): z;
            v0.x = fmaxf(fmaf(dv0, s0.x, q0.x), 0.0f);
            v0.y = fmaxf(fmaf(dv0, s0.y, q0.y), 0.0f);
            v1.x = fmaxf(fmaf(dv1, s1.x, q1.x), 0.0f);
            v1.y = fmaxf(fmaf(dv1, s1.y, q1.y), 0.0f);
            v2.x = fmaxf(fmaf(dv0, s2.x, q2.x), 0.0f);
            v2.y = fmaxf(fmaf(dv0, s2.y, q2.y), 0.0f);
            v3.x = fmaxf(fmaf(dv1, s3.x, q3.x), 0.0f);
            v3.y = fmaxf(fmaf(dv1, s3.y, q3.y), 0.0f);
        } else {
            float2 z = make_float2(0.f, 0.f);
            v0 = ok0 ? __ldg(reinterpret_cast<const float2*>(X0 + k0))     : z;
            v1 = ok1 ? __ldg(reinterpret_cast<const float2*>(X1 + k0))     : z;
            v2 = ok0 ? __ldg(reinterpret_cast<const float2*>(X0 + k0 + 8)) : z;
            v3 = ok1 ? __ldg(reinterpret_cast<const float2*>(X1 + k0 + 8)) : z;
        }

        uint32_t ah[4], al[4];
        cvt_split(v0, ah[0], al[0]);
        cvt_split(v1, ah[1], al[1]);
        cvt_split(v2, ah[2], al[2]);
        cvt_split(v3, ah[3], al[3]);

#pragma unroll
        for (int nt = 0; nt < NT; nt++) {
            int n0 = nt * 8 + g;
            uint32_t bh0 = *reinterpret_cast<const uint32_t*>(Bh + n0 * SB + k0);
            uint32_t bh1 = *reinterpret_cast<const uint32_t*>(Bh + n0 * SB + k0 + 8);
            uint32_t bl0 = *reinterpret_cast<const uint32_t*>(Bl + n0 * SB + k0);
            uint32_t bl1 = *reinterpret_cast<const uint32_t*>(Bl + n0 * SB + k0 + 8);
            MMA_BF16(acc[nt], ah, bh0, bh1);
            MMA_BF16(acc[nt], ah, bl0, bl1);
            MMA_BF16(acc[nt], al, bh0, bh1);
        }
    }

    // ---- epilogue ----
#pragma unroll
    for (int nt = 0; nt < NT; nt++) {
        int col = nt * 8 + t * 2;
        const float* a4 = acc[nt];
        if (ROOT) {
            float2 bb = *reinterpret_cast<const float2*>(Bias + col);
            if (ok0)
                *reinterpret_cast<float2*>(O + (size_t)r0 * NC + col) =
                    make_float2(a4[0] + bb.x, a4[1] + bb.y);
            if (ok1)
                *reinterpret_cast<float2*>(O + (size_t)r1 * NC + col) =
                    make_float2(a4[2] + bb.x, a4[3] + bb.y);
        } else {
            float2 z = make_float2(0.f, 0.f);
            if (ok0) {
                *reinterpret_cast<float2*>(O + (size_t)r0 * NC + col) =
                    make_float2(a4[0] * dv0, a4[1] * dv0);
                *reinterpret_cast<float2*>(S + (size_t)r0 * NC + col) = z;
            }
            if (ok1) {
                *reinterpret_cast<float2*>(O + (size_t)r1 * NC + col) =
                    make_float2(a4[2] * dv1, a4[3] * dv1);
                *reinterpret_cast<float2*>(S + (size_t)r1 * NC + col) = z;
            }
        }
    }
}

// ---------------------------------------------------------------------------
// Edge scatter: S[col] += G[row]  (fire-and-forget 128-bit reduction)
// ---------------------------------------------------------------------------
template <int FQ>
__global__ void scatter_add(const int* __restrict__ rowi, const int* __restrict__ coli,
                            const float* __restrict__ G, float* __restrict__ S, int total)
{
    int idx = blockIdx.x * blockDim.x + threadIdx.x;
    if (idx >= total) return;
    int e = idx / FQ;
    int c = idx - e * FQ;
    int r  = __ldg(rowi + e);
    int cl = __ldg(coli + e);
    float4 v = __ldg(reinterpret_cast<const float4*>(G + ((size_t)r * FQ + c) * 4));
    float* p = S + ((size_t)cl * FQ + c) * 4;
    asm volatile("red.global.add.v4.f32 [%0], {%1,%2,%3,%4};"
                 :: "l"(p), "f"(v.x), "f"(v.y), "f"(v.z), "f"(v.w) : "memory");
}

// ---------------------------------------------------------------------------
// Elementwise post: O = relu(dinv[node]*S + R)   (float4 lanes; R may == O)
// ---------------------------------------------------------------------------
template <int FQ>
__global__ void post_kernel(const float* __restrict__ S, const float* __restrict__ R,
                            const float* __restrict__ deg, float* __restrict__ O,
                            int total4, int N)
{
    int idx = blockIdx.x * blockDim.x + threadIdx.x;
    if (idx >= total4) return;
    int node = idx / FQ;
    float dv = dinv_of(deg, node, N);
    float4 s = *reinterpret_cast<const float4*>(S + (size_t)idx * 4);
    float4 r = *reinterpret_cast<const float4*>(R + (size_t)idx * 4);
    float4 o;
    o.x = fmaxf(fmaf(dv, s.x, r.x), 0.0f);
    o.y = fmaxf(fmaf(dv, s.y, r.y), 0.0f);
    o.z = fmaxf(fmaf(dv, s.z, r.z), 0.0f);
    o.w = fmaxf(fmaf(dv, s.w, r.w), 0.0f);
    *reinterpret_cast<float4*>(O + (size_t)idx * 4) = o;
}

// ---------------------------------------------------------------------------
extern "C" void kernel_launch(void* const* d_in, const int* in_sizes, int n_in,
                              void* d_out, int out_size)
{
    const float* x   = (const float*)d_in[0];
    const int*   ei  = (const int*)  d_in[1];
    const float* w1i = (const float*)d_in[2];
    const float* w1r = (const float*)d_in[3];
    const float* b1  = (const float*)d_in[4];
    const float* w2i = (const float*)d_in[5];
    const float* w2r = (const float*)d_in[6];
    const float* b2  = (const float*)d_in[7];
    float* out = (float*)d_out;

    const int E = in_sizes[1] / 2;
    const int N = out_size / 40;
    const int* row = ei;
    const int* col = ei + E;

    float *pdeg, *arena;
    cudaGetSymbolAddress((void**)&pdeg,  g_deg);
    cudaGetSymbolAddress((void**)&arena, g_arena);

    // Arena layout — NO aliasing between concurrently-live regions.
    float* pR1 = arena;                       // [0,64N)
    float* pS1 = arena + (size_t)N * 64;      // [64N,128N)
    float* pG1 = arena + (size_t)N * 128;     // [128N,192N)   g1 (dead after scatter1)
    float* pG2 = arena + (size_t)N * 128;     // [128N,168N)   g2 (over dead g1)
    float* pS2 = arena + (size_t)N * 168;     // [168N,208N)   fresh
    float* pR2 = out;                         // R2 -> d_out; post2 in place

    // Side stream + events (created once, outside any capture).
    static cudaStream_t s2 = nullptr;
    static cudaEvent_t evI = nullptr, evB = nullptr, evC = nullptr, evD = nullptr;
    if (s2 == nullptr) {
        cudaStreamCreateWithFlags(&s2, cudaStreamNonBlocking);
        cudaEventCreateWithFlags(&evI, cudaEventDisableTiming);
        cudaEventCreateWithFlags(&evB, cudaEventDisableTiming);
        cudaEventCreateWithFlags(&evC, cudaEventDisableTiming);
        cudaEventCreateWithFlags(&evD, cudaEventDisableTiming);
    }

    const int grid = (N + 127) / 128;

    // ---- main: deg, init GEMM 1 (full chip, no contention) ----
    cudaMemsetAsync(pdeg, 0, (size_t)N * sizeof(float));
    deg_kernel<<<(E + 255) / 256, 256>>>(col, pdeg, E);

    gemm_mma<128, 64, false, false><<<grid, 256>>>(
        x, nullptr, nullptr, w1i, nullptr, pdeg, pS1, pG1, N);

    // ---- fork AFTER gemm1i: R1 = x@W1r + b1 overlaps LTS-bound scatter1 ----
    cudaEventRecord(evI, 0);
    cudaStreamWaitEvent(s2, evI, 0);
    gemm_mma<128, 64, true, false><<<grid, 256, 0, s2>>>(
        x, nullptr, nullptr, w1r, b1, pdeg, nullptr, pR1, N);
    cudaEventRecord(evB, s2);

    // ---- main: scatter 1 (co-runs with gemm1r) ----
    {
        int total = E * 16;
        scatter_add<16><<<(total + 255) / 256, 256>>>(row, col, pG1, pS1, total);
    }

    // ---- fork: gemm2r (fused A = relu(dinv*S1+R1)) -> d_out, after scatter1
    cudaEventRecord(evC, 0);              // scatter1 done on main
    cudaStreamWaitEvent(s2, evC, 0);      // side already has R1 in-order
    gemm_mma<64, 40, true, true><<<grid, 256, 0, s2>>>(
        nullptr, pS1, pR1, w2r, b2, pdeg, nullptr, pR2, N);
    cudaEventRecord(evD, s2);

    // ---- main: gemm2i (fused A) -> g2, S2=0 ; then scatter2 ----
    cudaStreamWaitEvent(0, evB, 0);       // need R1 before fused A-loads
    gemm_mma<64, 40, false, true><<<grid, 256>>>(
        nullptr, pS1, pR1, w2i, nullptr, pdeg, pS2, pG2, N);
    {
        int total = E * 10;
        scatter_add<10><<<(total + 255) / 256, 256>>>(row, col, pG2, pS2, total);
    }

    // ---- join; out = relu(dinv*S2 + R2) in place over d_out ----
    cudaStreamWaitEvent(0, evD, 0);
    {
        int total4 = N * 10;
        post_kernel<10><<<(total4 + 255) / 256, 256>>>(pS2, pR2, pdeg, out, total4, N);
    }
}

// round 17
// speedup vs baseline: 1.0571x; 1.0571x over previous
#include <cuda_runtime.h>
#include <cuda_bf16.h>
#include <cstdint>

// ---------------------------------------------------------------------------
// BiARMA (2-layer ARMA GCN), N=100000, E=1e6, 128 -> 64 -> 40.
//
// dinv = rsqrt(deg(col)), 0 if deg==0  (precomputed on SIDE stream)
// g1   = x @ W1i  (UNSCALED; starts at t=0, no deg dependency)
// S1[c] += dinv[r] * g1[r]   per edge  (dinv folded into scatter1)
// R1   = x @ W1r + b1                  (side stream, overlaps gemm1i+scatter1)
// out1 = relu(dinv*S1 + R1)            (fused into layer-2 A-loads)
// g2   = dinv * (out1 @ W2i)           S2[c] += g2[row]
// R2   = out1 @ W2r + b2 -> d_out      (side stream, overlaps gemm2i+scatter2)
// out  = relu(dinv*S2 + R2)            (in place over d_out)
//
// GEMMs: mma.sync.m16n8k16 bf16, 2-term split (Ah*Bh + Ah*Bl + Al*Bh);
// A direct-from-global (optionally fused relu(dinv*S+R)), B in static smem.
// Scatter: red.global.add.v4.f32 — LTS-bound; overlapped with latency-bound
// root GEMMs only (R16 lesson: never pair it with L2-heavy work).
//
// Arena 83.6 MB, NO ALIASING between concurrently-live regions:
//   R1 [0,64N)   S1 [64N,128N)   g1 [128N,192N) (dead after scatter1)
//   g2 [128N,168N) (over dead g1)   S2 [168N,208N)   R2 -> d_out
// ---------------------------------------------------------------------------

static constexpr int MAXN = 100000;

__device__ float g_dinv [MAXN];          // deg counts, then rsqrt in place
__device__ float g_arena[(size_t)MAXN * 208];

// ---------------------------------------------------------------------------
__global__ void deg_kernel(const int* __restrict__ col, float* __restrict__ deg, int E) {
    int i = blockIdx.x * blockDim.x + threadIdx.x;
    if (i < E) atomicAdd(&deg[col[i]], 1.0f);
}

__global__ void dinv_kernel(float* __restrict__ d, int N) {
    int i = blockIdx.x * blockDim.x + threadIdx.x;
    if (i < N) {
        float v = d[i];
        d[i] = (v > 0.0f) ? rsqrtf(v) : 0.0f;
    }
}

// ---------------------------------------------------------------------------
#define MMA_BF16(c_, a_, b0_, b1_)                                          \
    asm volatile("mma.sync.aligned.m16n8k16.row.col.f32.bf16.bf16.f32 "     \
                 "{%0,%1,%2,%3}, {%4,%5,%6,%7}, {%8,%9}, {%0,%1,%2,%3};"    \
                 : "+f"((c_)[0]), "+f"((c_)[1]), "+f"((c_)[2]), "+f"((c_)[3]) \
                 : "r"((a_)[0]), "r"((a_)[1]), "r"((a_)[2]), "r"((a_)[3]),  \
                   "r"(b0_), "r"(b1_))

__device__ __forceinline__ void split_bf16(float v, __nv_bfloat16& h, __nv_bfloat16& l) {
    h = __float2bfloat16(v);
    l = __float2bfloat16(v - __bfloat162float(h));
}

// Split a float2 into packed bf16x2 hi + residual lo.
__device__ __forceinline__ void cvt_split(float2 v, uint32_t& hi, uint32_t& lo) {
    uint32_t h;
    asm("cvt.rn.bf16x2.f32 %0, %1, %2;" : "=r"(h) : "f"(v.y), "f"(v.x));
    float hx = __uint_as_float(h << 16);
    float hy = __uint_as_float(h & 0xFFFF0000u);
    float rx = v.x - hx;
    float ry = v.y - hy;
    uint32_t l;
    asm("cvt.rn.bf16x2.f32 %0, %1, %2;" : "=r"(l) : "f"(ry), "f"(rx));
    hi = h; lo = l;
}

__device__ __forceinline__ float dinv_at(const float* dinv, int node, int N) {
    return (node < N) ? dinv[node] : 0.0f;
}

// ---------------------------------------------------------------------------
// Tensor-core GEMM, A direct-from-global, B in static smem.
// FUSEA=false: A[n,k] = X[n,k]
// FUSEA=true : A[n,k] = relu(dinv[n]*SA[n,k] + RA[n,k])   (out1 on the fly)
// ROOT=false (INIT): O[n] = (SCALE? dinv[n] : 1)*(A@W)[n]  and  S[n] = 0
// ROOT=true        : O[n] = (A@W)[n] + bias
// Block: 256 threads (8 warps), tile = 128 rows; warp owns 16 rows x NC cols.
// ---------------------------------------------------------------------------
template <int K, int NC, bool ROOT, bool FUSEA, bool SCALE>
__global__ void __launch_bounds__(256)
gemm_mma(const float* __restrict__ X,
         const float* __restrict__ SA, const float* __restrict__ RA,
         const float* __restrict__ W,  const float* __restrict__ Bias,
         const float* __restrict__ dinv,
         float* __restrict__ S, float* __restrict__ O, int N)
{
    constexpr int SB = K + 8;
    constexpr int NT = NC / 8;

    __shared__ __nv_bfloat16 Bh[NC * SB];
    __shared__ __nv_bfloat16 Bl[NC * SB];

    const int tid  = threadIdx.x;
    const int base = blockIdx.x * 128;

    for (int i = tid; i < K * NC; i += 256) {
        int k = i / NC, n = i - k * NC;
        __nv_bfloat16 h, l;
        split_bf16(W[i], h, l);
        Bh[n * SB + k] = h;
        Bl[n * SB + k] = l;
    }
    __syncthreads();

    const int warp = tid >> 5, lane = tid & 31;
    const int g = lane >> 2, t = lane & 3;

    const int r0 = base + warp * 16 + g;
    const int r1 = r0 + 8;
    const bool ok0 = r0 < N, ok1 = r1 < N;

    const bool needD = FUSEA || (!ROOT && SCALE);
    const float dv0 = needD ? dinv_at(dinv, r0, N) : 0.0f;
    const float dv1 = needD ? dinv_at(dinv, r1, N) : 0.0f;

    const float* X0  = FUSEA ? nullptr : X + (size_t)r0 * K;
    const float* X1  = FUSEA ? nullptr : X + (size_t)r1 * K;
    const float* S0  = FUSEA ? SA + (size_t)r0 * K : nullptr;
    const float* S1p = FUSEA ? SA + (size_t)r1 * K : nullptr;
    const float* R0  = FUSEA ? RA + (size_t)r0 * K : nullptr;
    const float* R1p = FUSEA ? RA + (size_t)r1 * K : nullptr;

    float acc[NT][4];
#pragma unroll
    for (int nt = 0; nt < NT; nt++)
#pragma unroll
        for (int j = 0; j < 4; j++) acc[nt][j] = 0.0f;

#pragma unroll
    for (int ks = 0; ks < K; ks += 16) {
        const int k0 = ks + t * 2;

        float2 v0, v1, v2, v3;
        if (FUSEA) {
            float2 z = make_float2(0.f, 0.f);
            float2 s0 = ok0 ? __ldg(reinterpret_cast<const float2*>(S0 + k0))     : z;
            float2 s1 = ok1 ? __ldg(reinterpret_cast<const float2*>(S1p + k0))    : z;
            float2 s2 = ok0 ? __ldg(reinterpret_cast<const float2*>(S0 + k0 + 8)) : z;
            float2 s3 = ok1 ? __ldg(reinterpret_cast<const float2*>(S1p + k0 + 8)): z;
            float2 q0 = ok0 ? __ldg(reinterpret_cast<const float2*>(R0 + k0))     : z;
            float2 q1 = ok1 ? __ldg(reinterpret_cast<const float2*>(R1p + k0))    : z;
            float2 q2 = ok0 ? __ldg(reinterpret_cast<const float2*>(R0 + k0 + 8)) : z;
            float2 q3 = ok1 ? __ldg(reinterpret_cast<const float2*>(R1p + k0 + 8)): z;
            v0.x = fmaxf(fmaf(dv0, s0.x, q0.x), 0.0f);
            v0.y = fmaxf(fmaf(dv0, s0.y, q0.y), 0.0f);
            v1.x = fmaxf(fmaf(dv1, s1.x, q1.x), 0.0f);
            v1.y = fmaxf(fmaf(dv1, s1.y, q1.y), 0.0f);
            v2.x = fmaxf(fmaf(dv0, s2.x, q2.x), 0.0f);
            v2.y = fmaxf(fmaf(dv0, s2.y, q2.y), 0.0f);
            v3.x = fmaxf(fmaf(dv1, s3.x, q3.x), 0.0f);
            v3.y = fmaxf(fmaf(dv1, s3.y, q3.y), 0.0f);
        } else {
            float2 z = make_float2(0.f, 0.f);
            v0 = ok0 ? __ldg(reinterpret_cast<const float2*>(X0 + k0))     : z;
            v1 = ok1 ? __ldg(reinterpret_cast<const float2*>(X1 + k0))     : z;
            v2 = ok0 ? __ldg(reinterpret_cast<const float2*>(X0 + k0 + 8)) : z;
            v3 = ok1 ? __ldg(reinterpret_cast<const float2*>(X1 + k0 + 8)) : z;
        }

        uint32_t ah[4], al[4];
        cvt_split(v0, ah[0], al[0]);
        cvt_split(v1, ah[1], al[1]);
        cvt_split(v2, ah[2], al[2]);
        cvt_split(v3, ah[3], al[3]);

#pragma unroll
        for (int nt = 0; nt < NT; nt++) {
            int n0 = nt * 8 + g;
            uint32_t bh0 = *reinterpret_cast<const uint32_t*>(Bh + n0 * SB + k0);
            uint32_t bh1 = *reinterpret_cast<const uint32_t*>(Bh + n0 * SB + k0 + 8);
            uint32_t bl0 = *reinterpret_cast<const uint32_t*>(Bl + n0 * SB + k0);
            uint32_t bl1 = *reinterpret_cast<const uint32_t*>(Bl + n0 * SB + k0 + 8);
            MMA_BF16(acc[nt], ah, bh0, bh1);
            MMA_BF16(acc[nt], ah, bl0, bl1);
            MMA_BF16(acc[nt], al, bh0, bh1);
        }
    }

    // ---- epilogue ----
#pragma unroll
    for (int nt = 0; nt < NT; nt++) {
        int col = nt * 8 + t * 2;
        const float* a4 = acc[nt];
        if (ROOT) {
            float2 bb = *reinterpret_cast<const float2*>(Bias + col);
            if (ok0)
                *reinterpret_cast<float2*>(O + (size_t)r0 * NC + col) =
                    make_float2(a4[0] + bb.x, a4[1] + bb.y);
            if (ok1)
                *reinterpret_cast<float2*>(O + (size_t)r1 * NC + col) =
                    make_float2(a4[2] + bb.x, a4[3] + bb.y);
        } else {
            float2 z = make_float2(0.f, 0.f);
            float m0 = SCALE ? dv0 : 1.0f;
            float m1 = SCALE ? dv1 : 1.0f;
            if (ok0) {
                *reinterpret_cast<float2*>(O + (size_t)r0 * NC + col) =
                    make_float2(a4[0] * m0, a4[1] * m0);
                *reinterpret_cast<float2*>(S + (size_t)r0 * NC + col) = z;
            }
            if (ok1) {
                *reinterpret_cast<float2*>(O + (size_t)r1 * NC + col) =
                    make_float2(a4[2] * m1, a4[3] * m1);
                *reinterpret_cast<float2*>(S + (size_t)r1 * NC + col) = z;
            }
        }
    }
}

// ---------------------------------------------------------------------------
// Edge scatter: S[col] += (SCALE? dinv[row] : 1) * G[row]
// Fire-and-forget 128-bit reduction; one thread per (edge, float4 chunk).
// ---------------------------------------------------------------------------
template <int FQ, bool SCALE>
__global__ void scatter_add(const int* __restrict__ rowi, const int* __restrict__ coli,
                            const float* __restrict__ G, const float* __restrict__ dinv,
                            float* __restrict__ S, int total)
{
    int idx = blockIdx.x * blockDim.x + threadIdx.x;
    if (idx >= total) return;
    int e = idx / FQ;
    int c = idx - e * FQ;
    int r  = __ldg(rowi + e);
    int cl = __ldg(coli + e);
    float4 v = __ldg(reinterpret_cast<const float4*>(G + ((size_t)r * FQ + c) * 4));
    if (SCALE) {
        float dv = __ldg(dinv + r);      // 16-thread broadcast, L1 hit
        v.x *= dv; v.y *= dv; v.z *= dv; v.w *= dv;
    }
    float* p = S + ((size_t)cl * FQ + c) * 4;
    asm volatile("red.global.add.v4.f32 [%0], {%1,%2,%3,%4};"
                 :: "l"(p), "f"(v.x), "f"(v.y), "f"(v.z), "f"(v.w) : "memory");
}

// ---------------------------------------------------------------------------
// Elementwise post: O = relu(dinv[node]*S + R)   (float4 lanes; R may == O)
// ---------------------------------------------------------------------------
template <int FQ>
__global__ void post_kernel(const float* __restrict__ S, const float* __restrict__ R,
                            const float* __restrict__ dinv, float* __restrict__ O,
                            int total4, int N)
{
    int idx = blockIdx.x * blockDim.x + threadIdx.x;
    if (idx >= total4) return;
    int node = idx / FQ;
    float dv = dinv_at(dinv, node, N);
    float4 s = *reinterpret_cast<const float4*>(S + (size_t)idx * 4);
    float4 r = *reinterpret_cast<const float4*>(R + (size_t)idx * 4);
    float4 o;
    o.x = fmaxf(fmaf(dv, s.x, r.x), 0.0f);
    o.y = fmaxf(fmaf(dv, s.y, r.y), 0.0f);
    o.z = fmaxf(fmaf(dv, s.z, r.z), 0.0f);
    o.w = fmaxf(fmaf(dv, s.w, r.w), 0.0f);
    *reinterpret_cast<float4*>(O + (size_t)idx * 4) = o;
}

// ---------------------------------------------------------------------------
extern "C" void kernel_launch(void* const* d_in, const int* in_sizes, int n_in,
                              void* d_out, int out_size)
{
    const float* x   = (const float*)d_in[0];
    const int*   ei  = (const int*)  d_in[1];
    const float* w1i = (const float*)d_in[2];
    const float* w1r = (const float*)d_in[3];
    const float* b1  = (const float*)d_in[4];
    const float* w2i = (const float*)d_in[5];
    const float* w2r = (const float*)d_in[6];
    const float* b2  = (const float*)d_in[7];
    float* out = (float*)d_out;

    const int E = in_sizes[1] / 2;
    const int N = out_size / 40;
    const int* row = ei;
    const int* col = ei + E;

    float *pdinv, *arena;
    cudaGetSymbolAddress((void**)&pdinv, g_dinv);
    cudaGetSymbolAddress((void**)&arena, g_arena);

    // Arena layout — NO aliasing between concurrently-live regions.
    float* pR1 = arena;                       // [0,64N)
    float* pS1 = arena + (size_t)N * 64;      // [64N,128N)
    float* pG1 = arena + (size_t)N * 128;     // [128N,192N)   g1 (dead after scatter1)
    float* pG2 = arena + (size_t)N * 128;     // [128N,168N)   g2 (over dead g1)
    float* pS2 = arena + (size_t)N * 168;     // [168N,208N)   fresh
    float* pR2 = out;                         // R2 -> d_out; post2 in place

    // Side stream + events (created once, outside any capture).
    static cudaStream_t s2 = nullptr;
    static cudaEvent_t evA = nullptr, evDeg = nullptr, evB = nullptr,
                       evC = nullptr, evD = nullptr;
    if (s2 == nullptr) {
        cudaStreamCreateWithFlags(&s2, cudaStreamNonBlocking);
        cudaEventCreateWithFlags(&evA,   cudaEventDisableTiming);
        cudaEventCreateWithFlags(&evDeg, cudaEventDisableTiming);
        cudaEventCreateWithFlags(&evB,   cudaEventDisableTiming);
        cudaEventCreateWithFlags(&evC,   cudaEventDisableTiming);
        cudaEventCreateWithFlags(&evD,   cudaEventDisableTiming);
    }

    const int grid = (N + 127) / 128;

    // ---- fork side stream at t=0: deg/dinv prep, then gemm1r ----
    cudaEventRecord(evA, 0);
    cudaStreamWaitEvent(s2, evA, 0);
    cudaMemsetAsync(pdinv, 0, (size_t)N * sizeof(float), s2);
    deg_kernel <<<(E + 255) / 256, 256, 0, s2>>>(col, pdinv, E);
    dinv_kernel<<<(N + 255) / 256, 256, 0, s2>>>(pdinv, N);
    cudaEventRecord(evDeg, s2);
    // R1 = x@W1r + b1 (latency-bound; overlaps gemm1i then scatter1)
    gemm_mma<128, 64, true, false, false><<<grid, 256, 0, s2>>>(
        x, nullptr, nullptr, w1r, b1, pdinv, nullptr, pR1, N);
    cudaEventRecord(evB, s2);

    // ---- main: gemm1i starts at t=0 (UNSCALED -> no deg dependency) ----
    gemm_mma<128, 64, false, false, false><<<grid, 256>>>(
        x, nullptr, nullptr, w1i, nullptr, pdinv, pS1, pG1, N);

    // ---- main: scatter1 (applies dinv[row] per edge) ----
    cudaStreamWaitEvent(0, evDeg, 0);
    {
        int total = E * 16;
        scatter_add<16, true><<<(total + 255) / 256, 256>>>(row, col, pG1, pdinv, pS1, total);
    }

    // ---- fork: gemm2r (fused A = relu(dinv*S1+R1)) -> d_out, after scatter1
    cudaEventRecord(evC, 0);
    cudaStreamWaitEvent(s2, evC, 0);
    gemm_mma<64, 40, true, true, false><<<grid, 256, 0, s2>>>(
        nullptr, pS1, pR1, w2r, b2, pdinv, nullptr, pR2, N);
    cudaEventRecord(evD, s2);

    // ---- main: gemm2i (fused A, scaled) -> g2, S2=0 ; then scatter2 ----
    cudaStreamWaitEvent(0, evB, 0);       // need R1 before fused A-loads
    gemm_mma<64, 40, false, true, true><<<grid, 256>>>(
        nullptr, pS1, pR1, w2i, nullptr, pdinv, pS2, pG2, N);
    {
        int total = E * 10;
        scatter_add<10, false><<<(total + 255) / 256, 256>>>(row, col, pG2, pdinv, pS2, total);
    }

    // ---- join; out = relu(dinv*S2 + R2) in place over d_out ----
    cudaStreamWaitEvent(0, evD, 0);
    {
        int total4 = N * 10;
        post_kernel<10><<<(total4 + 255) / 256, 256>>>(pS2, pR2, pdinv, out, total4, N);
    }
}